// round 2
// baseline (speedup 1.0000x reference)
#include <cuda_runtime.h>
#include <cuda_bf16.h>
#include <cstdint>

#define EPS 1e-6f

// Shapes
#define B_ 4
#define N_ 8192
#define DIM_ 1024
#define H_ 16
#define DH_ 64
#define M_ (B_ * N_)            // 32768 rows
#define BIG (M_ * DIM_)         // 33554432 elems

// ---------------- scratch (static device globals; no allocation) ----------------
__device__ float g_q[BIG];
__device__ float g_k[BIG];
__device__ float g_v[BIG];
__device__ float g_qf[BIG];     // [bh, n, 64]
__device__ float g_kf[BIG];     // [bh, n, 64]
__device__ float g_attn[BIG];   // [b, n, 1024]
__device__ float g_kv[64 * 64 * 64];   // [bh, f, d]
__device__ float g_ksum[64 * 64];      // [bh, f]

// ---------------- generic tiled SGEMM: C = A[MxK] * B[KxN] (+bias) ----------------
// BM=BN=128, BK=16, 256 threads, 8x8 micro-tile. All dims divisible.
__global__ __launch_bounds__(256) void sgemm128(
    const float* __restrict__ A, const float* __restrict__ B,
    float* __restrict__ C, int M, int N, int K,
    const float* __restrict__ bias)
{
    __shared__ float As[16][128];
    __shared__ float Bs[16][128];

    const int tid  = threadIdx.x;
    const int brow = blockIdx.y;
    const int bcol = blockIdx.x;
    const int tx = tid % 16;      // col group
    const int ty = tid / 16;      // row group

    const float* Ab = A + (size_t)brow * 128 * K;
    const float* Bb = B + (size_t)bcol * 128;

    // A loads: 128x16 tile, 2048 floats, 2 float4/thread
    const int a_row = tid / 4;          // 0..63
    const int a_col = (tid % 4) * 4;    // 0..12
    // B loads: 16x128 tile, 2 float4/thread
    const int b_row = tid / 32;         // 0..7
    const int b_col = (tid % 32) * 4;   // 0..124

    float acc[8][8];
#pragma unroll
    for (int i = 0; i < 8; i++)
#pragma unroll
        for (int j = 0; j < 8; j++) acc[i][j] = 0.f;

    for (int k0 = 0; k0 < K; k0 += 16) {
#pragma unroll
        for (int s = 0; s < 2; s++) {
            float4 av = *(const float4*)(Ab + (size_t)(a_row + 64 * s) * K + k0 + a_col);
            As[a_col + 0][a_row + 64 * s] = av.x;
            As[a_col + 1][a_row + 64 * s] = av.y;
            As[a_col + 2][a_row + 64 * s] = av.z;
            As[a_col + 3][a_row + 64 * s] = av.w;
        }
#pragma unroll
        for (int s = 0; s < 2; s++) {
            float4 bv = *(const float4*)(Bb + (size_t)(k0 + b_row + 8 * s) * N + b_col);
            *(float4*)&Bs[b_row + 8 * s][b_col] = bv;
        }
        __syncthreads();

#pragma unroll
        for (int kk = 0; kk < 16; kk++) {
            float ar[8], br[8];
#pragma unroll
            for (int i = 0; i < 8; i++) ar[i] = As[kk][ty * 8 + i];
#pragma unroll
            for (int j = 0; j < 8; j++) br[j] = Bs[kk][tx * 8 + j];
#pragma unroll
            for (int i = 0; i < 8; i++)
#pragma unroll
                for (int j = 0; j < 8; j++)
                    acc[i][j] = fmaf(ar[i], br[j], acc[i][j]);
        }
        __syncthreads();
    }

#pragma unroll
    for (int i = 0; i < 8; i++) {
        size_t row = (size_t)brow * 128 + ty * 8 + i;
#pragma unroll
        for (int j = 0; j < 8; j += 4) {
            int col = bcol * 128 + tx * 8 + j;
            float4 o;
            o.x = acc[i][j + 0];
            o.y = acc[i][j + 1];
            o.z = acc[i][j + 2];
            o.w = acc[i][j + 3];
            if (bias) {
                o.x += bias[col + 0];
                o.y += bias[col + 1];
                o.z += bias[col + 2];
                o.w += bias[col + 3];
            }
            *(float4*)(C + row * N + col) = o;
        }
    }
}

// ---------------- feature map: outf[bh,n,f] = relu(inp[b,n,h*64+:] @ proj) + EPS ---
__global__ __launch_bounds__(256) void feature_map_kernel(
    const float* __restrict__ inp,   // [b, n, 1024]
    const float* __restrict__ proj,  // [64, 64]
    float* __restrict__ outf)        // [bh, n, 64]
{
    const int bh = blockIdx.y;       // 0..63
    const int b = bh / H_, h = bh % H_;
    const int n0 = blockIdx.x * 64;

    __shared__ float P[64 * 64];
    __shared__ float X[64][65];

    const int tid = threadIdx.x;
    for (int i = tid; i < 4096; i += 256) P[i] = proj[i];
    for (int i = tid; i < 4096; i += 256) {
        int r = i / 64, d = i % 64;
        X[r][d] = inp[((size_t)b * N_ + n0 + r) * DIM_ + h * DH_ + d];
    }
    __syncthreads();

    const int f = tid % 64;
    const int ry = tid / 64;  // 0..3
    for (int r = ry; r < 64; r += 4) {
        float s = 0.f;
#pragma unroll
        for (int d = 0; d < 64; d++) s = fmaf(X[r][d], P[d * 64 + f], s);
        s = fmaxf(s, 0.f) + EPS;
        outf[((size_t)bh * N_ + n0 + r) * 64 + f] = s;
    }
}

// ---------------- zero scratch ----------------
__global__ void zero_kv_kernel()
{
    int i = blockIdx.x * 256 + threadIdx.x;
    if (i < 64 * 64 * 64) g_kv[i] = 0.f;
    if (i < 64 * 64) g_ksum[i] = 0.f;
}

// ---------------- kv[f,d] += sum_n kf[n,f]*v[n,d]; ksum[f] += sum_n kf[n,f] -------
__global__ __launch_bounds__(256) void kv_accum_kernel(
    const float* __restrict__ kf,    // [bh, n, 64]
    const float* __restrict__ v)     // [b, n, 1024]
{
    const int bh = blockIdx.y;
    const int b = bh / H_, h = bh % H_;
    const int chunk = blockIdx.x;    // 16 chunks of 512 rows
    const int tid = threadIdx.x;

    __shared__ float kfs[2][64];
    __shared__ float vs[2][64];

    const int d = tid % 64;
    const int fg = tid / 64;         // f block: fg*16 .. fg*16+15

    float acc[16];
#pragma unroll
    for (int i = 0; i < 16; i++) acc[i] = 0.f;
    float ks = 0.f;

    const int n0 = chunk * 512;
    const int which = tid / 64;      // 0,1 -> kf rows; 2,3 -> v rows
    const int lane = tid % 64;
    const int rr = which % 2;

    for (int r = 0; r < 512; r += 2) {
        if (which < 2)
            kfs[rr][lane] = kf[((size_t)bh * N_ + n0 + r + rr) * 64 + lane];
        else
            vs[rr][lane] = v[((size_t)b * N_ + n0 + r + rr) * DIM_ + h * DH_ + lane];
        __syncthreads();
#pragma unroll
        for (int rr2 = 0; rr2 < 2; rr2++) {
            float vd = vs[rr2][d];
#pragma unroll
            for (int i = 0; i < 16; i++)
                acc[i] = fmaf(kfs[rr2][fg * 16 + i], vd, acc[i]);
            if (tid < 64) ks += kfs[rr2][tid];
        }
        __syncthreads();
    }

#pragma unroll
    for (int i = 0; i < 16; i++)
        atomicAdd(&g_kv[(size_t)bh * 4096 + (fg * 16 + i) * 64 + d], acc[i]);
    if (tid < 64) atomicAdd(&g_ksum[bh * 64 + tid], ks);
}

// ---------------- attn[b,n,h*64+d] = (qf @ kv) / (qf . ksum + EPS) ----------------
__global__ __launch_bounds__(256) void attn_out_kernel(
    const float* __restrict__ qf,    // [bh, n, 64]
    float* __restrict__ out)         // [b, n, 1024]
{
    const int bh = blockIdx.y;
    const int b = bh / H_, h = bh % H_;
    const int n0 = blockIdx.x * 64;
    const int tid = threadIdx.x;

    __shared__ float KV[64 * 64];
    __shared__ float KS[64];
    __shared__ float QF[64][65];

    for (int i = tid; i < 4096; i += 256) KV[i] = g_kv[(size_t)bh * 4096 + i];
    if (tid < 64) KS[tid] = g_ksum[bh * 64 + tid];
    for (int i = tid; i < 4096; i += 256) {
        int r = i / 64, f = i % 64;
        QF[r][f] = qf[((size_t)bh * N_ + n0 + r) * 64 + f];
    }
    __syncthreads();

    const int d = tid % 64;
    const int ry = tid / 64;
    for (int r = ry; r < 64; r += 4) {
        float num = 0.f, den = 0.f;
#pragma unroll
        for (int f = 0; f < 64; f++) {
            float q = QF[r][f];
            num = fmaf(q, KV[f * 64 + d], num);
            den = fmaf(q, KS[f], den);
        }
        out[((size_t)b * N_ + n0 + r) * DIM_ + h * DH_ + d] = num / (den + EPS);
    }
}

// ---------------- launch ----------------
extern "C" void kernel_launch(void* const* d_in, const int* in_sizes, int n_in,
                              void* d_out, int out_size)
{
    const float* x    = (const float*)d_in[0];
    const float* Wq   = (const float*)d_in[1];
    const float* Wk   = (const float*)d_in[2];
    const float* Wv   = (const float*)d_in[3];
    const float* proj = (const float*)d_in[4];
    const float* Wo   = (const float*)d_in[5];
    const float* bo   = (const float*)d_in[6];
    float* out = (float*)d_out;

    float *q, *k, *v, *qf, *kf, *attn;
    cudaGetSymbolAddress((void**)&q,    g_q);
    cudaGetSymbolAddress((void**)&k,    g_k);
    cudaGetSymbolAddress((void**)&v,    g_v);
    cudaGetSymbolAddress((void**)&qf,   g_qf);
    cudaGetSymbolAddress((void**)&kf,   g_kf);
    cudaGetSymbolAddress((void**)&attn, g_attn);

    dim3 gemm_grid(DIM_ / 128, M_ / 128);   // (8, 256)

    // QKV projections
    sgemm128<<<gemm_grid, 256>>>(x, Wq, q, M_, DIM_, DIM_, nullptr);
    sgemm128<<<gemm_grid, 256>>>(x, Wk, k, M_, DIM_, DIM_, nullptr);
    sgemm128<<<gemm_grid, 256>>>(x, Wv, v, M_, DIM_, DIM_, nullptr);

    // Feature maps
    dim3 fgrid(N_ / 64, B_ * H_);           // (128, 64)
    feature_map_kernel<<<fgrid, 256>>>(q, proj, qf);
    feature_map_kernel<<<fgrid, 256>>>(k, proj, kf);

    // kv + ksum reduction
    zero_kv_kernel<<<(64 * 64 * 64 + 255) / 256, 256>>>();
    kv_accum_kernel<<<dim3(16, B_ * H_), 256>>>(kf, v);

    // numerator / denominator
    attn_out_kernel<<<fgrid, 256>>>(qf, attn);

    // output projection + bias
    sgemm128<<<gemm_grid, 256>>>(attn, Wo, out, M_, DIM_, DIM_, bo);
}

// round 3
// speedup vs baseline: 1.0047x; 1.0047x over previous
#include <cuda_runtime.h>
#include <cuda_bf16.h>
#include <cstdint>

#define EPS 1e-6f

// Shapes
#define B_ 4
#define N_ 8192
#define DIM_ 1024
#define H_ 16
#define DH_ 64
#define M_ (B_ * N_)            // 32768 rows
#define BIG (M_ * DIM_)         // 33554432 elems

// ---------------- scratch (static device globals; no allocation) ----------------
__device__ float g_q[BIG];
__device__ float g_k[BIG];
__device__ float g_v[BIG];
__device__ float g_qf[BIG];     // [bh, n, 64]
__device__ float g_kf[BIG];     // [bh, n, 64]
__device__ float g_attn[BIG];   // [b, n, 1024]
__device__ float g_kv[64 * 64 * 64];   // [bh, f, d]
__device__ float g_ksum[64 * 64];      // [bh, f]

// ---------------- generic tiled SGEMM: C = A[MxK] * B[KxN] (+bias) ----------------
// BM=BN=128, BK=16, 256 threads, 8x8 micro-tile. All dims divisible.
__global__ __launch_bounds__(256) void sgemm128(
    const float* __restrict__ A, const float* __restrict__ B,
    float* __restrict__ C, int M, int N, int K,
    const float* __restrict__ bias)
{
    __shared__ float As[16][128];
    __shared__ float Bs[16][128];

    const int tid  = threadIdx.x;
    const int brow = blockIdx.y;
    const int bcol = blockIdx.x;
    const int tx = tid % 16;      // col group
    const int ty = tid / 16;      // row group

    const float* Ab = A + (size_t)brow * 128 * K;
    const float* Bb = B + (size_t)bcol * 128;

    // A loads: 128x16 tile, 2048 floats, 2 float4/thread
    const int a_row = tid / 4;          // 0..63
    const int a_col = (tid % 4) * 4;    // 0..12
    // B loads: 16x128 tile, 2 float4/thread
    const int b_row = tid / 32;         // 0..7
    const int b_col = (tid % 32) * 4;   // 0..124

    float acc[8][8];
#pragma unroll
    for (int i = 0; i < 8; i++)
#pragma unroll
        for (int j = 0; j < 8; j++) acc[i][j] = 0.f;

    for (int k0 = 0; k0 < K; k0 += 16) {
#pragma unroll
        for (int s = 0; s < 2; s++) {
            float4 av = *(const float4*)(Ab + (size_t)(a_row + 64 * s) * K + k0 + a_col);
            As[a_col + 0][a_row + 64 * s] = av.x;
            As[a_col + 1][a_row + 64 * s] = av.y;
            As[a_col + 2][a_row + 64 * s] = av.z;
            As[a_col + 3][a_row + 64 * s] = av.w;
        }
#pragma unroll
        for (int s = 0; s < 2; s++) {
            float4 bv = *(const float4*)(Bb + (size_t)(k0 + b_row + 8 * s) * N + b_col);
            *(float4*)&Bs[b_row + 8 * s][b_col] = bv;
        }
        __syncthreads();

#pragma unroll
        for (int kk = 0; kk < 16; kk++) {
            float ar[8], br[8];
#pragma unroll
            for (int i = 0; i < 8; i++) ar[i] = As[kk][ty * 8 + i];
#pragma unroll
            for (int j = 0; j < 8; j++) br[j] = Bs[kk][tx * 8 + j];
#pragma unroll
            for (int i = 0; i < 8; i++)
#pragma unroll
                for (int j = 0; j < 8; j++)
                    acc[i][j] = fmaf(ar[i], br[j], acc[i][j]);
        }
        __syncthreads();
    }

#pragma unroll
    for (int i = 0; i < 8; i++) {
        size_t row = (size_t)brow * 128 + ty * 8 + i;
#pragma unroll
        for (int j = 0; j < 8; j += 4) {
            int col = bcol * 128 + tx * 8 + j;
            float4 o;
            o.x = acc[i][j + 0];
            o.y = acc[i][j + 1];
            o.z = acc[i][j + 2];
            o.w = acc[i][j + 3];
            if (bias) {
                o.x += bias[col + 0];
                o.y += bias[col + 1];
                o.z += bias[col + 2];
                o.w += bias[col + 3];
            }
            *(float4*)(C + row * N + col) = o;
        }
    }
}

// ---------------- feature map: outf[bh,n,f] = relu(inp[b,n,h*64+:] @ proj) + EPS ---
__global__ __launch_bounds__(256) void feature_map_kernel(
    const float* __restrict__ inp,   // [b, n, 1024]
    const float* __restrict__ proj,  // [64, 64]
    float* __restrict__ outf)        // [bh, n, 64]
{
    const int bh = blockIdx.y;       // 0..63
    const int b = bh / H_, h = bh % H_;
    const int n0 = blockIdx.x * 64;

    __shared__ float P[64 * 64];
    __shared__ float X[64][65];

    const int tid = threadIdx.x;
    for (int i = tid; i < 4096; i += 256) P[i] = proj[i];
    for (int i = tid; i < 4096; i += 256) {
        int r = i / 64, d = i % 64;
        X[r][d] = inp[((size_t)b * N_ + n0 + r) * DIM_ + h * DH_ + d];
    }
    __syncthreads();

    const int f = tid % 64;
    const int ry = tid / 64;  // 0..3
    for (int r = ry; r < 64; r += 4) {
        float s = 0.f;
#pragma unroll
        for (int d = 0; d < 64; d++) s = fmaf(X[r][d], P[d * 64 + f], s);
        s = fmaxf(s, 0.f) + EPS;
        outf[((size_t)bh * N_ + n0 + r) * 64 + f] = s;
    }
}

// ---------------- zero scratch ----------------
__global__ void zero_kv_kernel()
{
    int i = blockIdx.x * 256 + threadIdx.x;
    if (i < 64 * 64 * 64) g_kv[i] = 0.f;
    if (i < 64 * 64) g_ksum[i] = 0.f;
}

// ---------------- kv[f,d] += sum_n kf[n,f]*v[n,d]; ksum[f] += sum_n kf[n,f] -------
__global__ __launch_bounds__(256) void kv_accum_kernel(
    const float* __restrict__ kf,    // [bh, n, 64]
    const float* __restrict__ v)     // [b, n, 1024]
{
    const int bh = blockIdx.y;
    const int b = bh / H_, h = bh % H_;
    const int chunk = blockIdx.x;    // 16 chunks of 512 rows
    const int tid = threadIdx.x;

    __shared__ float kfs[2][64];
    __shared__ float vs[2][64];

    const int d = tid % 64;
    const int fg = tid / 64;         // f block: fg*16 .. fg*16+15

    float acc[16];
#pragma unroll
    for (int i = 0; i < 16; i++) acc[i] = 0.f;
    float ks = 0.f;

    const int n0 = chunk * 512;
    const int which = tid / 64;      // 0,1 -> kf rows; 2,3 -> v rows
    const int lane = tid % 64;
    const int rr = which % 2;

    for (int r = 0; r < 512; r += 2) {
        if (which < 2)
            kfs[rr][lane] = kf[((size_t)bh * N_ + n0 + r + rr) * 64 + lane];
        else
            vs[rr][lane] = v[((size_t)b * N_ + n0 + r + rr) * DIM_ + h * DH_ + lane];
        __syncthreads();
#pragma unroll
        for (int rr2 = 0; rr2 < 2; rr2++) {
            float vd = vs[rr2][d];
#pragma unroll
            for (int i = 0; i < 16; i++)
                acc[i] = fmaf(kfs[rr2][fg * 16 + i], vd, acc[i]);
            if (tid < 64) ks += kfs[rr2][tid];
        }
        __syncthreads();
    }

#pragma unroll
    for (int i = 0; i < 16; i++)
        atomicAdd(&g_kv[(size_t)bh * 4096 + (fg * 16 + i) * 64 + d], acc[i]);
    if (tid < 64) atomicAdd(&g_ksum[bh * 64 + tid], ks);
}

// ---------------- attn[b,n,h*64+d] = (qf @ kv) / (qf . ksum + EPS) ----------------
__global__ __launch_bounds__(256) void attn_out_kernel(
    const float* __restrict__ qf,    // [bh, n, 64]
    float* __restrict__ out)         // [b, n, 1024]
{
    const int bh = blockIdx.y;
    const int b = bh / H_, h = bh % H_;
    const int n0 = blockIdx.x * 64;
    const int tid = threadIdx.x;

    __shared__ float KV[64 * 64];
    __shared__ float KS[64];
    __shared__ float QF[64][65];

    for (int i = tid; i < 4096; i += 256) KV[i] = g_kv[(size_t)bh * 4096 + i];
    if (tid < 64) KS[tid] = g_ksum[bh * 64 + tid];
    for (int i = tid; i < 4096; i += 256) {
        int r = i / 64, f = i % 64;
        QF[r][f] = qf[((size_t)bh * N_ + n0 + r) * 64 + f];
    }
    __syncthreads();

    const int d = tid % 64;
    const int ry = tid / 64;
    for (int r = ry; r < 64; r += 4) {
        float num = 0.f, den = 0.f;
#pragma unroll
        for (int f = 0; f < 64; f++) {
            float q = QF[r][f];
            num = fmaf(q, KV[f * 64 + d], num);
            den = fmaf(q, KS[f], den);
        }
        out[((size_t)b * N_ + n0 + r) * DIM_ + h * DH_ + d] = num / (den + EPS);
    }
}

// ---------------- launch ----------------
extern "C" void kernel_launch(void* const* d_in, const int* in_sizes, int n_in,
                              void* d_out, int out_size)
{
    const float* x    = (const float*)d_in[0];
    const float* Wq   = (const float*)d_in[1];
    const float* Wk   = (const float*)d_in[2];
    const float* Wv   = (const float*)d_in[3];
    const float* proj = (const float*)d_in[4];
    const float* Wo   = (const float*)d_in[5];
    const float* bo   = (const float*)d_in[6];
    float* out = (float*)d_out;

    float *q, *k, *v, *qf, *kf, *attn;
    cudaGetSymbolAddress((void**)&q,    g_q);
    cudaGetSymbolAddress((void**)&k,    g_k);
    cudaGetSymbolAddress((void**)&v,    g_v);
    cudaGetSymbolAddress((void**)&qf,   g_qf);
    cudaGetSymbolAddress((void**)&kf,   g_kf);
    cudaGetSymbolAddress((void**)&attn, g_attn);

    dim3 gemm_grid(DIM_ / 128, M_ / 128);   // (8, 256)

    // QKV projections
    sgemm128<<<gemm_grid, 256>>>(x, Wq, q, M_, DIM_, DIM_, nullptr);
    sgemm128<<<gemm_grid, 256>>>(x, Wk, k, M_, DIM_, DIM_, nullptr);
    sgemm128<<<gemm_grid, 256>>>(x, Wv, v, M_, DIM_, DIM_, nullptr);

    // Feature maps
    dim3 fgrid(N_ / 64, B_ * H_);           // (128, 64)
    feature_map_kernel<<<fgrid, 256>>>(q, proj, qf);
    feature_map_kernel<<<fgrid, 256>>>(k, proj, kf);

    // kv + ksum reduction
    zero_kv_kernel<<<(64 * 64 * 64 + 255) / 256, 256>>>();
    kv_accum_kernel<<<dim3(16, B_ * H_), 256>>>(kf, v);

    // numerator / denominator
    attn_out_kernel<<<fgrid, 256>>>(qf, attn);

    // output projection + bias
    sgemm128<<<gemm_grid, 256>>>(attn, Wo, out, M_, DIM_, DIM_, bo);
}

// round 4
// speedup vs baseline: 2.7516x; 2.7388x over previous
#include <cuda_runtime.h>
#include <cuda_bf16.h>
#include <cstdint>

#define EPS 1e-6f

// Shapes
#define B_ 4
#define N_ 8192
#define DIM_ 1024
#define H_ 16
#define M_ (B_ * N_)            // 32768 rows
#define BIG (M_ * DIM_)         // 33554432 elems

// ---------------- scratch (static device globals; no allocation) ----------------
__device__ float g_v[BIG];      // [b, n, 1024]
__device__ float g_qf[BIG];     // [b, n, 1024]  (head h occupies cols h*64..h*64+63)
__device__ float g_kf[BIG];     // [b, n, 1024]
__device__ float g_attn[BIG];   // [b, n, 1024]
__device__ float g_wqp[DIM_ * DIM_];
__device__ float g_wkp[DIM_ * DIM_];
__device__ float g_kv[64 * 64 * 64];   // [bh, f, d]
__device__ float g_ksum[64 * 64];      // [bh, f]

// ---------------- helpers ----------------
__device__ __forceinline__ uint32_t smem_u32(const void* p) {
    return (uint32_t)__cvta_generic_to_shared(p);
}

__device__ __forceinline__ void mma16816(float* c, const uint32_t* a, const uint32_t* b) {
    asm volatile(
        "mma.sync.aligned.m16n8k16.row.col.f32.bf16.bf16.f32 "
        "{%0,%1,%2,%3}, {%4,%5,%6,%7}, {%8,%9}, {%0,%1,%2,%3};\n"
        : "+f"(c[0]), "+f"(c[1]), "+f"(c[2]), "+f"(c[3])
        : "r"(a[0]), "r"(a[1]), "r"(a[2]), "r"(a[3]), "r"(b[0]), "r"(b[1]));
}

__device__ __forceinline__ void ldsm4(uint32_t* r, uint32_t addr) {
    asm volatile("ldmatrix.sync.aligned.m8n8.x4.shared.b16 {%0,%1,%2,%3}, [%4];"
        : "=r"(r[0]), "=r"(r[1]), "=r"(r[2]), "=r"(r[3]) : "r"(addr));
}
__device__ __forceinline__ void ldsm4t(uint32_t* r, uint32_t addr) {
    asm volatile("ldmatrix.sync.aligned.m8n8.x4.trans.shared.b16 {%0,%1,%2,%3}, [%4];"
        : "=r"(r[0]), "=r"(r[1]), "=r"(r[2]), "=r"(r[3]) : "r"(addr));
}

// split fp32 pair into bf16 hi pair and bf16 lo (residual) pair, packed as u32
__device__ __forceinline__ void split2(float a, float b, uint32_t& h, uint32_t& l) {
    __nv_bfloat16 ha = __float2bfloat16(a);
    __nv_bfloat16 hb = __float2bfloat16(b);
    __nv_bfloat16 la = __float2bfloat16(a - __bfloat162float(ha));
    __nv_bfloat16 lb = __float2bfloat16(b - __bfloat162float(hb));
    h = (uint32_t)__bfloat16_as_ushort(ha) | ((uint32_t)__bfloat16_as_ushort(hb) << 16);
    l = (uint32_t)__bfloat16_as_ushort(la) | ((uint32_t)__bfloat16_as_ushort(lb) << 16);
}

__device__ __forceinline__ void split8(float4 v0, float4 v1, uint4& h, uint4& l) {
    uint32_t h0, l0, h1, l1, h2, l2, h3, l3;
    split2(v0.x, v0.y, h0, l0);
    split2(v0.z, v0.w, h1, l1);
    split2(v1.x, v1.y, h2, l2);
    split2(v1.z, v1.w, h3, l3);
    h = make_uint4(h0, h1, h2, h3);
    l = make_uint4(l0, l1, l2, l3);
}

// ================= tensor-core GEMM: C = A[MxK] * B[KxN], fp32 via bf16x3 =======
// BM=128, BN=128, BK=32, 256 threads (8 warps, 2x4), warp tile 64x32.
// EPI: 0 = none, 1 = relu + EPS, 2 = +bias
#define ASTR 40   // halves per A-smem row (conflict-free for ldmatrix / stores)

template<int EPI>
__global__ __launch_bounds__(256) void gemm_bf16x3(
    const float* __restrict__ A, const float* __restrict__ Bm,
    float* __restrict__ C, int M, int N, int K,
    const float* __restrict__ bias)
{
    __shared__ __nv_bfloat16 Ah[128 * ASTR], Al[128 * ASTR];   // 10 KB each
    __shared__ __nv_bfloat16 Bh[32 * 128],  Bl[32 * 128];      //  8 KB each

    const int tid  = threadIdx.x;
    const int lane = tid & 31;
    const int wid  = tid >> 5;
    const int g    = lane >> 2;
    const int t    = lane & 3;
    const int warp_m = (wid & 1) * 64;
    const int warp_n = (wid >> 1) * 32;
    const int mb = blockIdx.y * 128;
    const int nb = blockIdx.x * 128;

    float acc[4][4][4];
#pragma unroll
    for (int mi = 0; mi < 4; mi++)
#pragma unroll
        for (int ni = 0; ni < 4; ni++)
#pragma unroll
            for (int c = 0; c < 4; c++) acc[mi][ni][c] = 0.f;

    // ldmatrix per-lane address components
    const int a_row_l  = (lane & 7) + ((lane >> 3) & 1) * 8;  // row within 16
    const int a_koff_l = ((lane >> 4) & 1) * 8;               // k offset (halves)
    const int b_krow_l = (lane & 7) + ((lane >> 3) & 1) * 8;  // k row within 16
    const int b_nchk_l = (lane >> 4) & 1;                     // +1 n-chunk (8 halves)

    for (int k0 = 0; k0 < K; k0 += 32) {
        // ---- stage A tile (128 x 32 fp32 -> hi/lo bf16) ----
#pragma unroll
        for (int s = 0; s < 4; s++) {
            int j = tid + s * 256;
            int r = j >> 3, c = (j & 7) << 2;
            float4 v = *(const float4*)(A + (size_t)(mb + r) * K + k0 + c);
            uint32_t h0, l0, h1, l1;
            split2(v.x, v.y, h0, l0);
            split2(v.z, v.w, h1, l1);
            *(uint32_t*)&Ah[r * ASTR + c]     = h0;
            *(uint32_t*)&Ah[r * ASTR + c + 2] = h1;
            *(uint32_t*)&Al[r * ASTR + c]     = l0;
            *(uint32_t*)&Al[r * ASTR + c + 2] = l1;
        }
        // ---- stage B tile (32 x 128 fp32 -> hi/lo bf16, XOR-swizzled 16B chunks) ----
#pragma unroll
        for (int s = 0; s < 2; s++) {
            int j  = tid + s * 256;          // 512 chunk-tasks
            int kk = j >> 4;                 // k row 0..31
            int c  = j & 15;                 // 16B chunk (8 halves) within row
            const float* src = Bm + (size_t)(k0 + kk) * N + nb + c * 8;
            float4 v0 = *(const float4*)(src);
            float4 v1 = *(const float4*)(src + 4);
            uint4 hc, lc;
            split8(v0, v1, hc, lc);
            int cx = c ^ (kk & 7);
            *(uint4*)&Bh[kk * 128 + cx * 8] = hc;
            *(uint4*)&Bl[kk * 128 + cx * 8] = lc;
        }
        __syncthreads();

#pragma unroll
        for (int ks = 0; ks < 2; ks++) {
            const int kb = ks * 16;
            uint32_t ah[4][4], al[4][4], bh[4][2], bl[4][2];
#pragma unroll
            for (int mi = 0; mi < 4; mi++) {
                int row = warp_m + mi * 16 + a_row_l;
                ldsm4(ah[mi], smem_u32(&Ah[row * ASTR + kb + a_koff_l]));
                ldsm4(al[mi], smem_u32(&Al[row * ASTR + kb + a_koff_l]));
            }
#pragma unroll
            for (int np = 0; np < 2; np++) {
                int krow  = kb + b_krow_l;
                int chunk = ((warp_n + np * 16) >> 3) + b_nchk_l;
                int cx    = chunk ^ (krow & 7);
                uint32_t r4[4];
                ldsm4t(r4, smem_u32(&Bh[krow * 128 + cx * 8]));
                bh[np * 2][0] = r4[0]; bh[np * 2][1] = r4[1];
                bh[np * 2 + 1][0] = r4[2]; bh[np * 2 + 1][1] = r4[3];
                ldsm4t(r4, smem_u32(&Bl[krow * 128 + cx * 8]));
                bl[np * 2][0] = r4[0]; bl[np * 2][1] = r4[1];
                bl[np * 2 + 1][0] = r4[2]; bl[np * 2 + 1][1] = r4[3];
            }
#pragma unroll
            for (int mi = 0; mi < 4; mi++)
#pragma unroll
                for (int ni = 0; ni < 4; ni++) {
                    mma16816(acc[mi][ni], ah[mi], bh[ni]);
                    mma16816(acc[mi][ni], ah[mi], bl[ni]);
                    mma16816(acc[mi][ni], al[mi], bh[ni]);
                }
        }
        __syncthreads();
    }

    // ---- epilogue ----
#pragma unroll
    for (int mi = 0; mi < 4; mi++) {
        int r0 = mb + warp_m + mi * 16 + g;
#pragma unroll
        for (int ni = 0; ni < 4; ni++) {
            int col = nb + warp_n + ni * 8 + 2 * t;
            float2 v0 = make_float2(acc[mi][ni][0], acc[mi][ni][1]);
            float2 v1 = make_float2(acc[mi][ni][2], acc[mi][ni][3]);
            if (EPI == 1) {
                v0.x = fmaxf(v0.x, 0.f) + EPS; v0.y = fmaxf(v0.y, 0.f) + EPS;
                v1.x = fmaxf(v1.x, 0.f) + EPS; v1.y = fmaxf(v1.y, 0.f) + EPS;
            }
            if (EPI == 2) {
                float b0 = bias[col], b1 = bias[col + 1];
                v0.x += b0; v0.y += b1; v1.x += b0; v1.y += b1;
            }
            *(float2*)(C + (size_t)r0 * N + col)       = v0;
            *(float2*)(C + (size_t)(r0 + 8) * N + col) = v1;
        }
    }
}

// ---------------- fold: Wp[:, h*64+f] = W[:, h*64+:] @ proj ----------------
__global__ __launch_bounds__(256) void fold_kernel(
    const float* __restrict__ W, const float* __restrict__ proj,
    float* __restrict__ Wp)
{
    const int dblk = blockIdx.x;   // 16 blocks of 64 rows
    const int h    = blockIdx.y;   // 16 heads
    const int tid  = threadIdx.x;

    __shared__ float P[64 * 64];
    __shared__ float Wb[64][65];

#pragma unroll
    for (int s = 0; s < 16; s++) {
        int j = tid + s * 256;
        P[j] = proj[j];
        int r = j >> 6, c = j & 63;
        Wb[r][c] = W[(size_t)(dblk * 64 + r) * DIM_ + h * 64 + c];
    }
    __syncthreads();

    const int f  = tid & 63;
    const int ds = tid >> 6;
    for (int dl = ds; dl < 64; dl += 4) {
        float acc = 0.f;
#pragma unroll 16
        for (int dd = 0; dd < 64; dd++)
            acc = fmaf(Wb[dl][dd], P[dd * 64 + f], acc);
        Wp[(size_t)(dblk * 64 + dl) * DIM_ + h * 64 + f] = acc;
    }
}

// ---------------- zero scratch ----------------
__global__ void zero_kv_kernel()
{
    int i = blockIdx.x * 256 + threadIdx.x;
    if (i < 64 * 64 * 64) g_kv[i] = 0.f;
    if (i < 64 * 64) g_ksum[i] = 0.f;
}

// ---------------- kv[f,d] += sum_n kf[n,f]*v[n,d]; ksum[f] += sum_n kf[n,f] -------
__global__ __launch_bounds__(256) void kv_accum_kernel(
    const float* __restrict__ kf,    // [b, n, 1024]
    const float* __restrict__ v)     // [b, n, 1024]
{
    const int bh = blockIdx.y;
    const int b = bh >> 4, h = bh & 15;
    const int n0 = blockIdx.x * 512;
    const int tid = threadIdx.x;

    __shared__ float kfs[32][64];
    __shared__ float vs[32][64];

    const int d  = tid & 63;
    const int fg = tid >> 6;

    float acc[16];
#pragma unroll
    for (int i = 0; i < 16; i++) acc[i] = 0.f;
    float ks = 0.f;

    for (int base = 0; base < 512; base += 32) {
#pragma unroll
        for (int s = 0; s < 2; s++) {
            int j = tid + s * 256;
            int r = j >> 4, c4 = (j & 15) << 2;
            size_t row = (size_t)(b * N_ + n0 + base + r);
            *(float4*)&kfs[r][c4] = *(const float4*)(kf + row * DIM_ + h * 64 + c4);
            *(float4*)&vs[r][c4]  = *(const float4*)(v  + row * DIM_ + h * 64 + c4);
        }
        __syncthreads();
#pragma unroll
        for (int r = 0; r < 32; r++) {
            float vd = vs[r][d];
#pragma unroll
            for (int i = 0; i < 16; i++)
                acc[i] = fmaf(kfs[r][fg * 16 + i], vd, acc[i]);
            if (tid < 64) ks += kfs[r][tid];
        }
        __syncthreads();
    }

#pragma unroll
    for (int i = 0; i < 16; i++)
        atomicAdd(&g_kv[(size_t)bh * 4096 + (fg * 16 + i) * 64 + d], acc[i]);
    if (tid < 64) atomicAdd(&g_ksum[bh * 64 + tid], ks);
}

// ---------------- attn[b,n,h*64+d] = (qf @ kv) / (qf . ksum + EPS) ----------------
__global__ __launch_bounds__(256) void attn_out_kernel(
    const float* __restrict__ qf,    // [b, n, 1024]
    float* __restrict__ out)         // [b, n, 1024]
{
    const int bh = blockIdx.y;
    const int b = bh >> 4, h = bh & 15;
    const int n0 = blockIdx.x * 64;
    const int tid = threadIdx.x;

    __shared__ float KVX[64][68];   // [f][d 0..63], ks at col 64
    __shared__ float QF[64][68];

#pragma unroll
    for (int s = 0; s < 4; s++) {
        int j = tid + s * 256;
        int f = j >> 4, d4 = (j & 15) << 2;
        *(float4*)&KVX[f][d4] = *(const float4*)(g_kv + (size_t)bh * 4096 + f * 64 + d4);
        *(float4*)&QF[f][d4]  = *(const float4*)(qf + (size_t)(b * N_ + n0 + f) * DIM_ + h * 64 + d4);
    }
    if (tid < 64) KVX[tid][64] = g_ksum[bh * 64 + tid];
    __syncthreads();

    const int d4 = (tid & 15) << 2;
    const int rb = tid >> 4;
#pragma unroll
    for (int p = 0; p < 4; p++) {
        int r = p * 16 + rb;
        float4 num = make_float4(0.f, 0.f, 0.f, 0.f);
        float den = 0.f;
#pragma unroll 16
        for (int f = 0; f < 64; f++) {
            float q = QF[r][f];
            float4 kvv = *(float4*)&KVX[f][d4];
            num.x = fmaf(q, kvv.x, num.x);
            num.y = fmaf(q, kvv.y, num.y);
            num.z = fmaf(q, kvv.z, num.z);
            num.w = fmaf(q, kvv.w, num.w);
            den   = fmaf(q, KVX[f][64], den);
        }
        float inv = 1.f / (den + EPS);
        float4 o = make_float4(num.x * inv, num.y * inv, num.z * inv, num.w * inv);
        *(float4*)(out + (size_t)(b * N_ + n0 + r) * DIM_ + h * 64 + d4) = o;
    }
}

// ---------------- launch ----------------
extern "C" void kernel_launch(void* const* d_in, const int* in_sizes, int n_in,
                              void* d_out, int out_size)
{
    const float* x    = (const float*)d_in[0];
    const float* Wq   = (const float*)d_in[1];
    const float* Wk   = (const float*)d_in[2];
    const float* Wv   = (const float*)d_in[3];
    const float* proj = (const float*)d_in[4];
    const float* Wo   = (const float*)d_in[5];
    const float* bo   = (const float*)d_in[6];
    float* out = (float*)d_out;

    float *v, *qf, *kf, *attn, *wqp, *wkp;
    cudaGetSymbolAddress((void**)&v,    g_v);
    cudaGetSymbolAddress((void**)&qf,   g_qf);
    cudaGetSymbolAddress((void**)&kf,   g_kf);
    cudaGetSymbolAddress((void**)&attn, g_attn);
    cudaGetSymbolAddress((void**)&wqp,  g_wqp);
    cudaGetSymbolAddress((void**)&wkp,  g_wkp);

    // fold proj into Wq / Wk (feature map becomes a GEMM epilogue)
    dim3 fold_grid(16, 16);
    fold_kernel<<<fold_grid, 256>>>(Wq, proj, wqp);
    fold_kernel<<<fold_grid, 256>>>(Wk, proj, wkp);

    dim3 gg(DIM_ / 128, M_ / 128);   // (8, 256)

    // qf = relu(x @ Wqp) + eps ; kf likewise ; v = x @ Wv
    gemm_bf16x3<1><<<gg, 256>>>(x, wqp, qf, M_, DIM_, DIM_, nullptr);
    gemm_bf16x3<1><<<gg, 256>>>(x, wkp, kf, M_, DIM_, DIM_, nullptr);
    gemm_bf16x3<0><<<gg, 256>>>(x, Wv,  v,  M_, DIM_, DIM_, nullptr);

    // kv + ksum reduction
    zero_kv_kernel<<<1024, 256>>>();
    kv_accum_kernel<<<dim3(16, 64), 256>>>(kf, v);

    // numerator / denominator
    attn_out_kernel<<<dim3(128, 64), 256>>>(qf, attn);

    // output projection + bias
    gemm_bf16x3<2><<<gg, 256>>>(attn, Wo, out, M_, DIM_, DIM_, bo);
}

// round 5
// speedup vs baseline: 3.1142x; 1.1318x over previous
#include <cuda_runtime.h>
#include <cuda_bf16.h>
#include <cstdint>

#define EPS 1e-6f

// Shapes
#define B_ 4
#define N_ 8192
#define DIM_ 1024
#define H_ 16
#define M_ (B_ * N_)            // 32768 rows
#define BIG (M_ * DIM_)         // 33554432 elems

// ---------------- scratch (static device globals; no allocation) ----------------
__device__ __nv_bfloat16 g_xh[BIG], g_xl[BIG];          // x hi/lo
__device__ float g_v[BIG];      // [b, n, 1024]
__device__ float g_qf[BIG];     // [b, n, 1024]
__device__ float g_kf[BIG];     // [b, n, 1024]
__device__ __nv_bfloat16 g_ah[BIG], g_al[BIG];          // attn hi/lo
__device__ float g_wqp[DIM_ * DIM_];
__device__ float g_wkp[DIM_ * DIM_];
__device__ __nv_bfloat16 g_wqph[DIM_ * DIM_], g_wqpl[DIM_ * DIM_];
__device__ __nv_bfloat16 g_wkph[DIM_ * DIM_], g_wkpl[DIM_ * DIM_];
__device__ __nv_bfloat16 g_wvh[DIM_ * DIM_],  g_wvl[DIM_ * DIM_];
__device__ __nv_bfloat16 g_woh[DIM_ * DIM_],  g_wol[DIM_ * DIM_];
__device__ float g_kv[64 * 64 * 64];   // [bh, f, d]
__device__ float g_ksum[64 * 64];      // [bh, f]

// ---------------- helpers ----------------
__device__ __forceinline__ uint32_t smem_u32(const void* p) {
    return (uint32_t)__cvta_generic_to_shared(p);
}

__device__ __forceinline__ void mma16816(float* c, const uint32_t* a, const uint32_t* b) {
    asm volatile(
        "mma.sync.aligned.m16n8k16.row.col.f32.bf16.bf16.f32 "
        "{%0,%1,%2,%3}, {%4,%5,%6,%7}, {%8,%9}, {%0,%1,%2,%3};\n"
        : "+f"(c[0]), "+f"(c[1]), "+f"(c[2]), "+f"(c[3])
        : "r"(a[0]), "r"(a[1]), "r"(a[2]), "r"(a[3]), "r"(b[0]), "r"(b[1]));
}

__device__ __forceinline__ void ldsm4(uint32_t* r, uint32_t addr) {
    asm volatile("ldmatrix.sync.aligned.m8n8.x4.shared.b16 {%0,%1,%2,%3}, [%4];"
        : "=r"(r[0]), "=r"(r[1]), "=r"(r[2]), "=r"(r[3]) : "r"(addr));
}
__device__ __forceinline__ void ldsm4t(uint32_t* r, uint32_t addr) {
    asm volatile("ldmatrix.sync.aligned.m8n8.x4.trans.shared.b16 {%0,%1,%2,%3}, [%4];"
        : "=r"(r[0]), "=r"(r[1]), "=r"(r[2]), "=r"(r[3]) : "r"(addr));
}

__device__ __forceinline__ void cp16(void* dst, const void* src) {
    asm volatile("cp.async.cg.shared.global [%0], [%1], 16;"
        :: "r"(smem_u32(dst)), "l"(src));
}
__device__ __forceinline__ void cp_commit() {
    asm volatile("cp.async.commit_group;");
}

// split fp32 pair into bf16 hi pair and bf16 lo (residual) pair, packed as u32
__device__ __forceinline__ void split2(float a, float b, uint32_t& h, uint32_t& l) {
    __nv_bfloat16 ha = __float2bfloat16(a);
    __nv_bfloat16 hb = __float2bfloat16(b);
    __nv_bfloat16 la = __float2bfloat16(a - __bfloat162float(ha));
    __nv_bfloat16 lb = __float2bfloat16(b - __bfloat162float(hb));
    h = (uint32_t)__bfloat16_as_ushort(ha) | ((uint32_t)__bfloat16_as_ushort(hb) << 16);
    l = (uint32_t)__bfloat16_as_ushort(la) | ((uint32_t)__bfloat16_as_ushort(lb) << 16);
}

// ---------------- split: fp32 -> bf16 hi/lo ----------------
__global__ __launch_bounds__(256) void split_kernel(
    const float* __restrict__ src, __nv_bfloat16* __restrict__ h,
    __nv_bfloat16* __restrict__ l, int n4)
{
    int i = blockIdx.x * 256 + threadIdx.x;
    if (i < n4) {
        float4 v = ((const float4*)src)[i];
        uint32_t h0, l0, h1, l1;
        split2(v.x, v.y, h0, l0);
        split2(v.z, v.w, h1, l1);
        ((uint2*)h)[i] = make_uint2(h0, h1);
        ((uint2*)l)[i] = make_uint2(l0, l1);
    }
}

// ================= pipelined tensor-core GEMM: C = A*B, bf16x3, cp.async ========
// BM=128, BN=128, BK=32, 256 threads (8 warps 2x4), warp tile 64x32, 3 stages.
#define STAGES 3
#define ASTR 40                 // halves per A-smem row (80B, 16B-aligned, conflict-free)
#define A_STG (128 * ASTR)      // 5120 halves
#define B_STG (32 * 128)        // 4096 halves
#define GEMM_SMEM ((size_t)STAGES * (2 * A_STG + 2 * B_STG) * 2)   // 110592 B

template<int EPI>   // 0 = none, 1 = relu+EPS, 2 = +bias
__global__ __launch_bounds__(256, 2) void gemm_pipe(
    const __nv_bfloat16* __restrict__ Agh, const __nv_bfloat16* __restrict__ Agl,
    const __nv_bfloat16* __restrict__ Bgh, const __nv_bfloat16* __restrict__ Bgl,
    float* __restrict__ C, int M, int N, int K,
    const float* __restrict__ bias)
{
    extern __shared__ __nv_bfloat16 sm[];
    __nv_bfloat16* Ah = sm;
    __nv_bfloat16* Al = Ah + STAGES * A_STG;
    __nv_bfloat16* Bh = Al + STAGES * A_STG;
    __nv_bfloat16* Bl = Bh + STAGES * B_STG;

    const int tid  = threadIdx.x;
    const int lane = tid & 31;
    const int wid  = tid >> 5;
    const int g    = lane >> 2;
    const int t    = lane & 3;
    const int warp_m = (wid & 1) * 64;
    const int warp_n = (wid >> 1) * 32;
    const int mb = blockIdx.y * 128;
    const int nb = blockIdx.x * 128;

    float acc[4][4][4];
#pragma unroll
    for (int mi = 0; mi < 4; mi++)
#pragma unroll
        for (int ni = 0; ni < 4; ni++)
#pragma unroll
            for (int c = 0; c < 4; c++) acc[mi][ni][c] = 0.f;

    // per-lane ldmatrix address components
    const int a_row_l  = (lane & 7) + ((lane >> 3) & 1) * 8;
    const int a_koff_l = ((lane >> 4) & 1) * 8;
    const int b_krow_l = (lane & 7) + ((lane >> 3) & 1) * 8;
    const int b_nchk_l = (lane >> 4) & 1;

    // precompute load task indices (8 x 16B cp.async per thread per stage)
    // A: 1024 chunks (hi 512 + lo 512): r = 0..127, c = 0..3
    // B: 1024 chunks: kk = 0..31, c = 0..15, swizzled
    const int KT = K >> 5;

    auto load_stage = [&](int stg, int k0) {
#pragma unroll
        for (int s = 0; s < 4; s++) {
            int j = tid + s * 256;
            int half = j >> 9, jj = j & 511;
            int r = jj >> 2, c = jj & 3;
            const __nv_bfloat16* src = (half ? Agl : Agh) + (size_t)(mb + r) * K + k0 + c * 8;
            __nv_bfloat16* dst = (half ? Al : Ah) + stg * A_STG + r * ASTR + c * 8;
            cp16(dst, src);
        }
#pragma unroll
        for (int s = 0; s < 4; s++) {
            int j = tid + s * 256;
            int half = j >> 9, jj = j & 511;
            int kk = jj >> 4, c = jj & 15;
            int cx = c ^ (kk & 7);
            const __nv_bfloat16* src = (half ? Bgl : Bgh) + (size_t)(k0 + kk) * N + nb + c * 8;
            __nv_bfloat16* dst = (half ? Bl : Bh) + stg * B_STG + kk * 128 + cx * 8;
            cp16(dst, src);
        }
        cp_commit();
    };

    int load_k = 0;
    for (; load_k < STAGES - 1; ++load_k) load_stage(load_k, load_k * 32);

    for (int i = 0; i < KT; i++) {
        asm volatile("cp.async.wait_group %0;" :: "n"(STAGES - 2));
        __syncthreads();
        if (load_k < KT) { load_stage(load_k % STAGES, load_k * 32); load_k++; }

        const int stg = i % STAGES;
        const __nv_bfloat16* sAh = Ah + stg * A_STG;
        const __nv_bfloat16* sAl = Al + stg * A_STG;
        const __nv_bfloat16* sBh = Bh + stg * B_STG;
        const __nv_bfloat16* sBl = Bl + stg * B_STG;

#pragma unroll
        for (int ks = 0; ks < 2; ks++) {
            const int kb = ks * 16;
            uint32_t ah[4][4], al[4][4], bh[4][2], bl[4][2];
#pragma unroll
            for (int mi = 0; mi < 4; mi++) {
                int row = warp_m + mi * 16 + a_row_l;
                ldsm4(ah[mi], smem_u32(&sAh[row * ASTR + kb + a_koff_l]));
                ldsm4(al[mi], smem_u32(&sAl[row * ASTR + kb + a_koff_l]));
            }
#pragma unroll
            for (int np = 0; np < 2; np++) {
                int krow  = kb + b_krow_l;
                int chunk = ((warp_n + np * 16) >> 3) + b_nchk_l;
                int cx    = chunk ^ (krow & 7);
                uint32_t r4[4];
                ldsm4t(r4, smem_u32(&sBh[krow * 128 + cx * 8]));
                bh[np * 2][0] = r4[0]; bh[np * 2][1] = r4[1];
                bh[np * 2 + 1][0] = r4[2]; bh[np * 2 + 1][1] = r4[3];
                ldsm4t(r4, smem_u32(&sBl[krow * 128 + cx * 8]));
                bl[np * 2][0] = r4[0]; bl[np * 2][1] = r4[1];
                bl[np * 2 + 1][0] = r4[2]; bl[np * 2 + 1][1] = r4[3];
            }
#pragma unroll
            for (int mi = 0; mi < 4; mi++)
#pragma unroll
                for (int ni = 0; ni < 4; ni++) {
                    mma16816(acc[mi][ni], ah[mi], bh[ni]);
                    mma16816(acc[mi][ni], ah[mi], bl[ni]);
                    mma16816(acc[mi][ni], al[mi], bh[ni]);
                }
        }
    }

    // ---- epilogue ----
#pragma unroll
    for (int mi = 0; mi < 4; mi++) {
        int r0 = mb + warp_m + mi * 16 + g;
#pragma unroll
        for (int ni = 0; ni < 4; ni++) {
            int col = nb + warp_n + ni * 8 + 2 * t;
            float2 v0 = make_float2(acc[mi][ni][0], acc[mi][ni][1]);
            float2 v1 = make_float2(acc[mi][ni][2], acc[mi][ni][3]);
            if (EPI == 1) {
                v0.x = fmaxf(v0.x, 0.f) + EPS; v0.y = fmaxf(v0.y, 0.f) + EPS;
                v1.x = fmaxf(v1.x, 0.f) + EPS; v1.y = fmaxf(v1.y, 0.f) + EPS;
            }
            if (EPI == 2) {
                float b0 = bias[col], b1 = bias[col + 1];
                v0.x += b0; v0.y += b1; v1.x += b0; v1.y += b1;
            }
            *(float2*)(C + (size_t)r0 * N + col)       = v0;
            *(float2*)(C + (size_t)(r0 + 8) * N + col) = v1;
        }
    }
}

// ---------------- fold: Wp[:, h*64+f] = W[:, h*64+:] @ proj ----------------
__global__ __launch_bounds__(256) void fold_kernel(
    const float* __restrict__ W, const float* __restrict__ proj,
    float* __restrict__ Wp)
{
    const int dblk = blockIdx.x;
    const int h    = blockIdx.y;
    const int tid  = threadIdx.x;

    __shared__ float P[64 * 64];
    __shared__ float Wb[64][65];

#pragma unroll
    for (int s = 0; s < 16; s++) {
        int j = tid + s * 256;
        P[j] = proj[j];
        int r = j >> 6, c = j & 63;
        Wb[r][c] = W[(size_t)(dblk * 64 + r) * DIM_ + h * 64 + c];
    }
    __syncthreads();

    const int f  = tid & 63;
    const int ds = tid >> 6;
    for (int dl = ds; dl < 64; dl += 4) {
        float acc = 0.f;
#pragma unroll 16
        for (int dd = 0; dd < 64; dd++)
            acc = fmaf(Wb[dl][dd], P[dd * 64 + f], acc);
        Wp[(size_t)(dblk * 64 + dl) * DIM_ + h * 64 + f] = acc;
    }
}

// ---------------- zero scratch ----------------
__global__ void zero_kv_kernel()
{
    int i = blockIdx.x * 256 + threadIdx.x;
    if (i < 64 * 64 * 64) g_kv[i] = 0.f;
    if (i < 64 * 64) g_ksum[i] = 0.f;
}

// ---------------- kv[f,d] += sum_n kf[n,f]*v[n,d]; ksum[f] += sum_n kf[n,f] -------
__global__ __launch_bounds__(256) void kv_accum_kernel(
    const float* __restrict__ kf, const float* __restrict__ v)
{
    const int bh = blockIdx.y;
    const int b = bh >> 4, h = bh & 15;
    const int n0 = blockIdx.x * 512;
    const int tid = threadIdx.x;

    __shared__ float kfs[32][64];
    __shared__ float vs[32][64];

    const int d  = tid & 63;
    const int fg = tid >> 6;

    float acc[16];
#pragma unroll
    for (int i = 0; i < 16; i++) acc[i] = 0.f;
    float ks = 0.f;

    for (int base = 0; base < 512; base += 32) {
#pragma unroll
        for (int s = 0; s < 2; s++) {
            int j = tid + s * 256;
            int r = j >> 4, c4 = (j & 15) << 2;
            size_t row = (size_t)(b * N_ + n0 + base + r);
            *(float4*)&kfs[r][c4] = *(const float4*)(kf + row * DIM_ + h * 64 + c4);
            *(float4*)&vs[r][c4]  = *(const float4*)(v  + row * DIM_ + h * 64 + c4);
        }
        __syncthreads();
#pragma unroll
        for (int r = 0; r < 32; r++) {
            float vd = vs[r][d];
#pragma unroll
            for (int i = 0; i < 16; i++)
                acc[i] = fmaf(kfs[r][fg * 16 + i], vd, acc[i]);
            if (tid < 64) ks += kfs[r][tid];
        }
        __syncthreads();
    }

#pragma unroll
    for (int i = 0; i < 16; i++)
        atomicAdd(&g_kv[(size_t)bh * 4096 + (fg * 16 + i) * 64 + d], acc[i]);
    if (tid < 64) atomicAdd(&g_ksum[bh * 64 + tid], ks);
}

// ---- attn = (qf @ kv) / (qf.ksum + EPS), written directly as bf16 hi/lo ---------
__global__ __launch_bounds__(256) void attn_out_kernel(
    const float* __restrict__ qf,
    __nv_bfloat16* __restrict__ outh, __nv_bfloat16* __restrict__ outl)
{
    const int bh = blockIdx.y;
    const int b = bh >> 4, h = bh & 15;
    const int n0 = blockIdx.x * 64;
    const int tid = threadIdx.x;

    __shared__ float KVX[64][68];
    __shared__ float QF[64][68];

#pragma unroll
    for (int s = 0; s < 4; s++) {
        int j = tid + s * 256;
        int f = j >> 4, d4 = (j & 15) << 2;
        *(float4*)&KVX[f][d4] = *(const float4*)(g_kv + (size_t)bh * 4096 + f * 64 + d4);
        *(float4*)&QF[f][d4]  = *(const float4*)(qf + (size_t)(b * N_ + n0 + f) * DIM_ + h * 64 + d4);
    }
    if (tid < 64) KVX[tid][64] = g_ksum[bh * 64 + tid];
    __syncthreads();

    const int d4 = (tid & 15) << 2;
    const int rb = tid >> 4;
#pragma unroll
    for (int p = 0; p < 4; p++) {
        int r = p * 16 + rb;
        float4 num = make_float4(0.f, 0.f, 0.f, 0.f);
        float den = 0.f;
#pragma unroll 16
        for (int f = 0; f < 64; f++) {
            float q = QF[r][f];
            float4 kvv = *(float4*)&KVX[f][d4];
            num.x = fmaf(q, kvv.x, num.x);
            num.y = fmaf(q, kvv.y, num.y);
            num.z = fmaf(q, kvv.z, num.z);
            num.w = fmaf(q, kvv.w, num.w);
            den   = fmaf(q, KVX[f][64], den);
        }
        float inv = 1.f / (den + EPS);
        float4 o = make_float4(num.x * inv, num.y * inv, num.z * inv, num.w * inv);
        uint32_t h0, l0, h1, l1;
        split2(o.x, o.y, h0, l0);
        split2(o.z, o.w, h1, l1);
        size_t idx = (size_t)(b * N_ + n0 + r) * DIM_ + h * 64 + d4;
        *(uint2*)(outh + idx) = make_uint2(h0, h1);
        *(uint2*)(outl + idx) = make_uint2(l0, l1);
    }
}

// ---------------- launch ----------------
extern "C" void kernel_launch(void* const* d_in, const int* in_sizes, int n_in,
                              void* d_out, int out_size)
{
    const float* x    = (const float*)d_in[0];
    const float* Wq   = (const float*)d_in[1];
    const float* Wk   = (const float*)d_in[2];
    const float* Wv   = (const float*)d_in[3];
    const float* proj = (const float*)d_in[4];
    const float* Wo   = (const float*)d_in[5];
    const float* bo   = (const float*)d_in[6];
    float* out = (float*)d_out;

    __nv_bfloat16 *xh, *xl, *ah, *al;
    __nv_bfloat16 *wqph, *wqpl, *wkph, *wkpl, *wvh, *wvl, *woh, *wol;
    float *v, *qf, *kf, *wqp, *wkp;
    cudaGetSymbolAddress((void**)&xh,   g_xh);
    cudaGetSymbolAddress((void**)&xl,   g_xl);
    cudaGetSymbolAddress((void**)&v,    g_v);
    cudaGetSymbolAddress((void**)&qf,   g_qf);
    cudaGetSymbolAddress((void**)&kf,   g_kf);
    cudaGetSymbolAddress((void**)&ah,   g_ah);
    cudaGetSymbolAddress((void**)&al,   g_al);
    cudaGetSymbolAddress((void**)&wqp,  g_wqp);
    cudaGetSymbolAddress((void**)&wkp,  g_wkp);
    cudaGetSymbolAddress((void**)&wqph, g_wqph);
    cudaGetSymbolAddress((void**)&wqpl, g_wqpl);
    cudaGetSymbolAddress((void**)&wkph, g_wkph);
    cudaGetSymbolAddress((void**)&wkpl, g_wkpl);
    cudaGetSymbolAddress((void**)&wvh,  g_wvh);
    cudaGetSymbolAddress((void**)&wvl,  g_wvl);
    cudaGetSymbolAddress((void**)&woh,  g_woh);
    cudaGetSymbolAddress((void**)&wol,  g_wol);

    cudaFuncSetAttribute(gemm_pipe<0>, cudaFuncAttributeMaxDynamicSharedMemorySize, GEMM_SMEM);
    cudaFuncSetAttribute(gemm_pipe<1>, cudaFuncAttributeMaxDynamicSharedMemorySize, GEMM_SMEM);
    cudaFuncSetAttribute(gemm_pipe<2>, cudaFuncAttributeMaxDynamicSharedMemorySize, GEMM_SMEM);

    // fold proj into Wq / Wk
    dim3 fold_grid(16, 16);
    fold_kernel<<<fold_grid, 256>>>(Wq, proj, wqp);
    fold_kernel<<<fold_grid, 256>>>(Wk, proj, wkp);

    // pre-split operands to bf16 hi/lo
    split_kernel<<<BIG / 4 / 256, 256>>>(x, xh, xl, BIG / 4);
    const int W4 = DIM_ * DIM_ / 4;
    split_kernel<<<W4 / 256, 256>>>(wqp, wqph, wqpl, W4);
    split_kernel<<<W4 / 256, 256>>>(wkp, wkph, wkpl, W4);
    split_kernel<<<W4 / 256, 256>>>(Wv,  wvh,  wvl,  W4);
    split_kernel<<<W4 / 256, 256>>>(Wo,  woh,  wol,  W4);

    dim3 gg(DIM_ / 128, M_ / 128);   // (8, 256)

    // qf = relu(x @ Wqp) + eps ; kf likewise ; v = x @ Wv
    gemm_pipe<1><<<gg, 256, GEMM_SMEM>>>(xh, xl, wqph, wqpl, qf, M_, DIM_, DIM_, nullptr);
    gemm_pipe<1><<<gg, 256, GEMM_SMEM>>>(xh, xl, wkph, wkpl, kf, M_, DIM_, DIM_, nullptr);
    gemm_pipe<0><<<gg, 256, GEMM_SMEM>>>(xh, xl, wvh,  wvl,  v,  M_, DIM_, DIM_, nullptr);

    // kv + ksum reduction
    zero_kv_kernel<<<1024, 256>>>();
    kv_accum_kernel<<<dim3(16, 64), 256>>>(kf, v);

    // numerator / denominator -> bf16 hi/lo directly
    attn_out_kernel<<<dim3(128, 64), 256>>>(qf, ah, al);

    // output projection + bias
    gemm_pipe<2><<<gg, 256, GEMM_SMEM>>>(ah, al, woh, wol, out, M_, DIM_, DIM_, bo);
}